// round 1
// baseline (speedup 1.0000x reference)
#include <cuda_runtime.h>

// Problem constants
#define B_   4
#define S_   1024
#define D_   1024
#define H_   16
#define HD_  64
#define QKVN 3072            // 3*D
#define M_   (B_ * S_)       // 4096 flattened rows

// Scratch (static device globals — allocation-free per harness rules)
__device__ float g_qkv[(size_t)M_ * QKVN];   // [b,s, h*192 + {q:0..64, k:64..128, v:128..192}]
__device__ float g_ctx[(size_t)M_ * D_];     // [b,s, h*64+d]

// ---------------------------------------------------------------------------
// 128x128x8 fp32 GEMM with bias: C[M x N] = A[M x K] @ Bm[K x N] + bias[N]
// 256 threads, 8x8 microtile per thread. M, N, K all multiples of 128/8.
// ---------------------------------------------------------------------------
__device__ __forceinline__ void sgemm128_body(
    const float* __restrict__ A, const float* __restrict__ Bm,
    const float* __restrict__ bias, float* __restrict__ C,
    int N, int K)
{
    __shared__ float As[8][128];
    __shared__ float Bs[8][128];

    const int tid = threadIdx.x;
    const int tx  = tid & 15;          // 0..15 -> N direction
    const int ty  = tid >> 4;          // 0..15 -> M direction
    const int bx  = blockIdx.x;        // N tile
    const int by  = blockIdx.y;        // M tile

    const int arow = tid >> 1;         // 0..127
    const int acol = (tid & 1) * 4;    // 0 or 4
    const int brow = tid >> 5;         // 0..7
    const int bcol = (tid & 31) * 4;   // 0..124

    const float* Ab = A + (size_t)(by * 128) * K;
    const float* Bb = Bm + bx * 128;

    float acc[8][8];
#pragma unroll
    for (int i = 0; i < 8; i++)
#pragma unroll
        for (int j = 0; j < 8; j++) acc[i][j] = 0.f;

    for (int kt = 0; kt < K; kt += 8) {
        float4 a4 = *(const float4*)(Ab + (size_t)arow * K + kt + acol);
        float4 b4 = *(const float4*)(Bb + (size_t)(kt + brow) * N + bcol);
        __syncthreads();
        As[acol + 0][arow] = a4.x;
        As[acol + 1][arow] = a4.y;
        As[acol + 2][arow] = a4.z;
        As[acol + 3][arow] = a4.w;
        *(float4*)(&Bs[brow][bcol]) = b4;
        __syncthreads();
#pragma unroll
        for (int k = 0; k < 8; k++) {
            float4 aA = *(const float4*)&As[k][ty * 8];
            float4 aB = *(const float4*)&As[k][ty * 8 + 4];
            float4 bA = *(const float4*)&Bs[k][tx * 8];
            float4 bB = *(const float4*)&Bs[k][tx * 8 + 4];
            float a[8] = {aA.x, aA.y, aA.z, aA.w, aB.x, aB.y, aB.z, aB.w};
            float b[8] = {bA.x, bA.y, bA.z, bA.w, bB.x, bB.y, bB.z, bB.w};
#pragma unroll
            for (int i = 0; i < 8; i++)
#pragma unroll
                for (int j = 0; j < 8; j++) acc[i][j] += a[i] * b[j];
        }
    }

    const int row0 = by * 128 + ty * 8;
    const int col0 = bx * 128 + tx * 8;
    float bb[8];
#pragma unroll
    for (int j = 0; j < 8; j++) bb[j] = bias[col0 + j];
#pragma unroll
    for (int i = 0; i < 8; i++) {
        float4 r0 = make_float4(acc[i][0] + bb[0], acc[i][1] + bb[1],
                                acc[i][2] + bb[2], acc[i][3] + bb[3]);
        float4 r1 = make_float4(acc[i][4] + bb[4], acc[i][5] + bb[5],
                                acc[i][6] + bb[6], acc[i][7] + bb[7]);
        *(float4*)(C + (size_t)(row0 + i) * N + col0)     = r0;
        *(float4*)(C + (size_t)(row0 + i) * N + col0 + 4) = r1;
    }
}

__global__ __launch_bounds__(256) void qkv_gemm_kernel(
    const float* __restrict__ x, const float* __restrict__ W,
    const float* __restrict__ bias)
{
    sgemm128_body(x, W, bias, g_qkv, QKVN, D_);
}

__global__ __launch_bounds__(256) void out_gemm_kernel(
    const float* __restrict__ W, const float* __restrict__ bias,
    float* __restrict__ out)
{
    sgemm128_body(g_ctx, W, bias, out, D_, D_);
}

// ---------------------------------------------------------------------------
// Fused attention: per block = (b, h, 16 q rows).
// scores tile [16][1024] resident in SMEM; K/V streamed in 64-row tiles
// (padded stride 65 to avoid bank conflicts). Writes att once, ctx to g_ctx.
// ---------------------------------------------------------------------------
#define QT 16
#define KT 64
#define KSTRIDE 65
#define ATTN_SMEM ((QT * S_ + QT * HD_ + KT * KSTRIDE) * 4)

__global__ __launch_bounds__(256) void attn_kernel(
    const float* __restrict__ mask, float* __restrict__ att)
{
    extern __shared__ float sm[];
    float* sc = sm;                      // [QT][S_]
    float* qs = sc + QT * S_;            // [QT][HD_]
    float* ks = qs + QT * HD_;           // [KT][KSTRIDE]  (reused for V)

    const int b  = blockIdx.z;
    const int h  = blockIdx.y;
    const int q0 = blockIdx.x * QT;
    const int tid = threadIdx.x;
    const float scale = 0.125f;          // 1/sqrt(64)

    // load Q tile (pre-scaled)
    for (int idx = tid; idx < QT * HD_; idx += 256) {
        int qi = idx >> 6, d = idx & 63;
        qs[idx] = g_qkv[(size_t)(b * S_ + q0 + qi) * QKVN + h * 192 + d] * scale;
    }

    const int q     = tid >> 4;          // 0..15
    const int kb    = (tid & 15) * 4;    // k-offset within tile (score phase)
    const int dbase = kb;                // d-offset (ctx phase)

    // ---- score phase ----
    for (int kt = 0; kt < S_; kt += KT) {
        __syncthreads();
        // load K tile [64 x 64] (coalesced float4), store padded
        for (int v = tid; v < (KT * HD_) / 4; v += 256) {
            int kl = v >> 4;
            int d  = (v & 15) << 2;
            float4 t = *(const float4*)(g_qkv +
                (size_t)(b * S_ + kt + kl) * QKVN + h * 192 + 64 + d);
            float* p = ks + kl * KSTRIDE + d;
            p[0] = t.x; p[1] = t.y; p[2] = t.z; p[3] = t.w;
        }
        __syncthreads();

        float a0 = 0.f, a1 = 0.f, a2 = 0.f, a3 = 0.f;
#pragma unroll 8
        for (int d = 0; d < HD_; d++) {
            float qv = qs[q * HD_ + d];
            a0 += qv * ks[(kb + 0) * KSTRIDE + d];
            a1 += qv * ks[(kb + 1) * KSTRIDE + d];
            a2 += qv * ks[(kb + 2) * KSTRIDE + d];
            a3 += qv * ks[(kb + 3) * KSTRIDE + d];
        }
        const float* mrow = mask + ((size_t)(b * S_) + (q0 + q)) * S_ + kt + kb;
        sc[q * S_ + kt + kb + 0] = a0 + mrow[0];
        sc[q * S_ + kt + kb + 1] = a1 + mrow[1];
        sc[q * S_ + kt + kb + 2] = a2 + mrow[2];
        sc[q * S_ + kt + kb + 3] = a3 + mrow[3];
    }
    __syncthreads();

    // ---- softmax: one warp per 2 rows ----
    {
        const int w = tid >> 5, lane = tid & 31;
        for (int r = w; r < QT; r += 8) {
            float* row = sc + r * S_;
            float m = -1e30f;
            for (int k = lane; k < S_; k += 32) m = fmaxf(m, row[k]);
#pragma unroll
            for (int o = 16; o; o >>= 1) m = fmaxf(m, __shfl_xor_sync(~0u, m, o));
            float sum = 0.f;
            for (int k = lane; k < S_; k += 32) {
                float e = __expf(row[k] - m);
                row[k] = e;
                sum += e;
            }
#pragma unroll
            for (int o = 16; o; o >>= 1) sum += __shfl_xor_sync(~0u, sum, o);
            float inv = 1.f / sum;
            for (int k = lane; k < S_; k += 32) row[k] *= inv;
        }
    }
    __syncthreads();

    // ---- write att (coalesced) ----
    {
        float* abase = att + ((size_t)(b * H_ + h) * S_ + q0) * S_;
        for (int idx = tid; idx < QT * S_; idx += 256) {
            abase[(size_t)(idx >> 10) * S_ + (idx & 1023)] = sc[idx];
        }
    }

    // ---- ctx = att @ V ----
    float c0 = 0.f, c1 = 0.f, c2 = 0.f, c3 = 0.f;
    for (int kt = 0; kt < S_; kt += KT) {
        __syncthreads();
        for (int v = tid; v < (KT * HD_) / 4; v += 256) {
            int kl = v >> 4;
            int d  = (v & 15) << 2;
            float4 t = *(const float4*)(g_qkv +
                (size_t)(b * S_ + kt + kl) * QKVN + h * 192 + 128 + d);
            float* p = ks + kl * KSTRIDE + d;
            p[0] = t.x; p[1] = t.y; p[2] = t.z; p[3] = t.w;
        }
        __syncthreads();
#pragma unroll 8
        for (int kl = 0; kl < KT; kl++) {
            float p = sc[q * S_ + kt + kl];
            c0 += p * ks[kl * KSTRIDE + dbase + 0];
            c1 += p * ks[kl * KSTRIDE + dbase + 1];
            c2 += p * ks[kl * KSTRIDE + dbase + 2];
            c3 += p * ks[kl * KSTRIDE + dbase + 3];
        }
    }
    float4 cv = make_float4(c0, c1, c2, c3);
    *(float4*)(g_ctx + (size_t)(b * S_ + q0 + q) * D_ + h * HD_ + dbase) = cv;
}

// ---------------------------------------------------------------------------
extern "C" void kernel_launch(void* const* d_in, const int* in_sizes, int n_in,
                              void* d_out, int out_size)
{
    const float* x    = (const float*)d_in[0];
    const float* mask = (const float*)d_in[1];
    const float* Wqkv = (const float*)d_in[2];
    const float* bqkv = (const float*)d_in[3];
    const float* Wo   = (const float*)d_in[4];
    const float* bo   = (const float*)d_in[5];

    float* out = (float*)d_out;                       // [B,S,D]
    float* att = out + (size_t)B_ * S_ * D_;          // [B,H,S,S]

    // opt-in to >48KB dynamic smem for the attention kernel (idempotent)
    cudaFuncSetAttribute(attn_kernel,
                         cudaFuncAttributeMaxDynamicSharedMemorySize, ATTN_SMEM);

    // 1) fused QKV projection
    {
        dim3 grid(QKVN / 128, M_ / 128);
        qkv_gemm_kernel<<<grid, 256>>>(x, Wqkv, bqkv);
    }
    // 2) fused attention (scores + softmax + att write + ctx)
    {
        dim3 grid(S_ / QT, H_, B_);
        attn_kernel<<<grid, 256, ATTN_SMEM>>>(mask, att);
    }
    // 3) output projection
    {
        dim3 grid(D_ / 128, M_ / 128);
        out_gemm_kernel<<<grid, 256>>>(Wo, bo, out);
    }
}

// round 3
// speedup vs baseline: 3.1989x; 3.1989x over previous
#include <cuda_runtime.h>
#include <cstdint>

// Problem constants
#define B_   4
#define S_   1024
#define D_   1024
#define H_   16
#define HD_  64
#define QKVN 3072
#define M_   (B_ * S_)

// Scratch (static device globals — allocation-free per harness rules)
__device__ float g_qkv[(size_t)M_ * QKVN];   // [b,s, h*192 + {q,k,v}*64]
__device__ float g_ctx[(size_t)M_ * D_];     // [b,s, h*64+d]

// ---------------------------------------------------------------------------
// helpers
// ---------------------------------------------------------------------------
__device__ __forceinline__ float to_tf32(float x) {
    uint32_t u;
    asm("cvt.rna.tf32.f32 %0, %1;" : "=r"(u) : "f"(x));
    return __uint_as_float(u);
}

__device__ __forceinline__ void mma_tf32(float* d, const uint32_t* a, const uint32_t* b) {
    asm volatile(
        "mma.sync.aligned.m16n8k8.row.col.f32.tf32.tf32.f32 "
        "{%0,%1,%2,%3}, {%4,%5,%6,%7}, {%8,%9}, {%0,%1,%2,%3};\n"
        : "+f"(d[0]), "+f"(d[1]), "+f"(d[2]), "+f"(d[3])
        : "r"(a[0]), "r"(a[1]), "r"(a[2]), "r"(a[3]), "r"(b[0]), "r"(b[1]));
}

// ---------------------------------------------------------------------------
// tf32 GEMM: C[M x N] = A[M x K] @ Bm[K x N] + bias[N]
// 128x128 block tile, BK=32, 8 warps (4x2), warp tile 32x64.
// As[m][k] stride 36 (conflict-free: bank = 4g+a), Bs[k][n] stride 136 (8a+g).
// ---------------------------------------------------------------------------
#define BK   32
#define ASTR 36
#define BSTR 136

__device__ __forceinline__ void gemm_tf32_body(
    const float* __restrict__ A, const float* __restrict__ Bm,
    const float* __restrict__ bias, float* __restrict__ C,
    int N, int K)
{
    __shared__ float As[128 * ASTR];
    __shared__ float Bs[BK * BSTR];

    const int tid  = threadIdx.x;
    const int lane = tid & 31;
    const int wid  = tid >> 5;
    const int wm   = (wid & 3) * 32;   // warp M offset in tile
    const int wn   = (wid >> 2) * 64;  // warp N offset in tile
    const int bx   = blockIdx.x * 128;
    const int by   = blockIdx.y * 128;

    const int g = lane >> 2;   // group id 0..7
    const int a = lane & 3;    // in-group 0..3

    float acc[2][8][4];
#pragma unroll
    for (int i = 0; i < 2; i++)
#pragma unroll
        for (int j = 0; j < 8; j++)
#pragma unroll
            for (int v = 0; v < 4; v++) acc[i][j][v] = 0.f;

    const int arow0 = tid >> 3;          // 0..31, step 32 -> 4 rows
    const int acol  = (tid & 7) * 4;     // 0..28
    const int brow0 = tid >> 5;          // 0..7, step 8 -> 4 rows
    const int bcol  = (tid & 31) * 4;    // 0..124

    for (int k0 = 0; k0 < K; k0 += BK) {
        // --- stage: global -> regs ---
        float4 av[4], bv[4];
#pragma unroll
        for (int i = 0; i < 4; i++)
            av[i] = *(const float4*)(A + (size_t)(by + arow0 + 32 * i) * K + k0 + acol);
#pragma unroll
        for (int i = 0; i < 4; i++)
            bv[i] = *(const float4*)(Bm + (size_t)(k0 + brow0 + 8 * i) * N + bx + bcol);

        __syncthreads();
        // --- regs -> smem (tf32) ---
#pragma unroll
        for (int i = 0; i < 4; i++) {
            float4 t = av[i];
            t.x = to_tf32(t.x); t.y = to_tf32(t.y); t.z = to_tf32(t.z); t.w = to_tf32(t.w);
            *(float4*)(As + (arow0 + 32 * i) * ASTR + acol) = t;
        }
#pragma unroll
        for (int i = 0; i < 4; i++) {
            float4 t = bv[i];
            t.x = to_tf32(t.x); t.y = to_tf32(t.y); t.z = to_tf32(t.z); t.w = to_tf32(t.w);
            *(float4*)(Bs + (brow0 + 8 * i) * BSTR + bcol) = t;
        }
        __syncthreads();

        // --- compute ---
#pragma unroll
        for (int kk = 0; kk < BK; kk += 8) {
            uint32_t af[2][4], bf[8][2];
#pragma unroll
            for (int i = 0; i < 2; i++) {
                int r = wm + i * 16 + g;
                af[i][0] = __float_as_uint(As[(r)     * ASTR + kk + a]);
                af[i][1] = __float_as_uint(As[(r + 8) * ASTR + kk + a]);
                af[i][2] = __float_as_uint(As[(r)     * ASTR + kk + 4 + a]);
                af[i][3] = __float_as_uint(As[(r + 8) * ASTR + kk + 4 + a]);
            }
#pragma unroll
            for (int j = 0; j < 8; j++) {
                int n = wn + j * 8 + g;
                bf[j][0] = __float_as_uint(Bs[(kk + a)     * BSTR + n]);
                bf[j][1] = __float_as_uint(Bs[(kk + 4 + a) * BSTR + n]);
            }
#pragma unroll
            for (int i = 0; i < 2; i++)
#pragma unroll
                for (int j = 0; j < 8; j++)
                    mma_tf32(acc[i][j], af[i], bf[j]);
        }
    }

    // --- epilogue with bias ---
#pragma unroll
    for (int i = 0; i < 2; i++) {
        int row = by + wm + i * 16 + g;
#pragma unroll
        for (int j = 0; j < 8; j++) {
            int col = bx + wn + j * 8 + a * 2;
            float b0 = bias[col], b1 = bias[col + 1];
            *(float2*)(C + (size_t)row * N + col) =
                make_float2(acc[i][j][0] + b0, acc[i][j][1] + b1);
            *(float2*)(C + (size_t)(row + 8) * N + col) =
                make_float2(acc[i][j][2] + b0, acc[i][j][3] + b1);
        }
    }
}

__global__ __launch_bounds__(256) void qkv_gemm_kernel(
    const float* __restrict__ x, const float* __restrict__ W,
    const float* __restrict__ bias)
{
    gemm_tf32_body(x, W, bias, g_qkv, QKVN, D_);
}

__global__ __launch_bounds__(256) void out_gemm_kernel(
    const float* __restrict__ W, const float* __restrict__ bias,
    float* __restrict__ out)
{
    gemm_tf32_body(g_ctx, W, bias, out, D_, D_);
}

// ---------------------------------------------------------------------------
// Fused attention on tensor cores. Block = (b, h, 16 q rows), 8 warps.
// sc[16][1032] fp32 scores; qs[16][72], kv[128][72] tf32 tiles.
// scores: warp w owns 16 cols of each 128-kv chunk (2 n8 frags).
// ctx: warp w owns 8 of the 64 head dims (1 n8 frag), K accumulated 1024.
// ---------------------------------------------------------------------------
#define QT    16
#define KVT   128
#define SCSTR 1032
#define KVSTR 72
#define ATTN_SMEM ((QT * SCSTR + QT * KVSTR + KVT * KVSTR) * 4)

__global__ __launch_bounds__(256) void attn_kernel(
    const float* __restrict__ mask, float* __restrict__ att)
{
    extern __shared__ float sm[];
    float* sc = sm;                      // [QT][SCSTR]
    float* qs = sc + QT * SCSTR;         // [QT][KVSTR]
    float* kv = qs + QT * KVSTR;         // [KVT][KVSTR]

    const int b   = blockIdx.z;
    const int h   = blockIdx.y;
    const int q0  = blockIdx.x * QT;
    const int tid = threadIdx.x;
    const int lane = tid & 31;
    const int w    = tid >> 5;
    const int g = lane >> 2;
    const int a = lane & 3;

    // load Q tile (pre-scaled, tf32)
    for (int idx = tid; idx < QT * HD_; idx += 256) {
        int qi = idx >> 6, d = idx & 63;
        qs[qi * KVSTR + d] =
            to_tf32(g_qkv[(size_t)(b * S_ + q0 + qi) * QKVN + h * 192 + d] * 0.125f);
    }

    // ---- scores ----
    for (int c = 0; c < 8; c++) {
        __syncthreads();
        // load K chunk [128 x 64] -> kv (tf32)
#pragma unroll
        for (int i = 0; i < 8; i++) {
            int v = tid + 256 * i;
            int row = v >> 4, col = (v & 15) * 4;
            float4 t = *(const float4*)(g_qkv +
                (size_t)(b * S_ + c * KVT + row) * QKVN + h * 192 + 64 + col);
            t.x = to_tf32(t.x); t.y = to_tf32(t.y); t.z = to_tf32(t.z); t.w = to_tf32(t.w);
            *(float4*)(kv + row * KVSTR + col) = t;
        }
        __syncthreads();

        float acc2[2][4] = {{0.f,0.f,0.f,0.f},{0.f,0.f,0.f,0.f}};
#pragma unroll
        for (int ks = 0; ks < 8; ks++) {
            int k0 = ks * 8;
            uint32_t af[4], bf[2][2];
            af[0] = __float_as_uint(qs[(g)     * KVSTR + k0 + a]);
            af[1] = __float_as_uint(qs[(g + 8) * KVSTR + k0 + a]);
            af[2] = __float_as_uint(qs[(g)     * KVSTR + k0 + 4 + a]);
            af[3] = __float_as_uint(qs[(g + 8) * KVSTR + k0 + 4 + a]);
#pragma unroll
            for (int j = 0; j < 2; j++) {
                int n = w * 16 + j * 8 + g;          // chunk-local kv row
                bf[j][0] = __float_as_uint(kv[n * KVSTR + k0 + a]);
                bf[j][1] = __float_as_uint(kv[n * KVSTR + k0 + 4 + a]);
            }
            mma_tf32(acc2[0], af, bf[0]);
            mma_tf32(acc2[1], af, bf[1]);
        }
        // write scores + mask into sc
#pragma unroll
        for (int j = 0; j < 2; j++) {
            int colL = w * 16 + j * 8 + a * 2;       // local col in chunk
            int colG = c * 128 + colL;               // global k col
            const float* m0 = mask + ((size_t)(b * S_) + (q0 + g)) * S_ + colG;
            const float* m1 = mask + ((size_t)(b * S_) + (q0 + g + 8)) * S_ + colG;
            sc[(g)     * SCSTR + colG]     = acc2[j][0] + m0[0];
            sc[(g)     * SCSTR + colG + 1] = acc2[j][1] + m0[1];
            sc[(g + 8) * SCSTR + colG]     = acc2[j][2] + m1[0];
            sc[(g + 8) * SCSTR + colG + 1] = acc2[j][3] + m1[1];
        }
    }
    __syncthreads();

    // ---- softmax: one warp per 2 rows ----
    for (int r = w; r < QT; r += 8) {
        float* row = sc + r * SCSTR;
        float m = -1e30f;
        for (int k = lane; k < S_; k += 32) m = fmaxf(m, row[k]);
#pragma unroll
        for (int o = 16; o; o >>= 1) m = fmaxf(m, __shfl_xor_sync(~0u, m, o));
        float sum = 0.f;
        for (int k = lane; k < S_; k += 32) {
            float e = __expf(row[k] - m);
            row[k] = e;
            sum += e;
        }
#pragma unroll
        for (int o = 16; o; o >>= 1) sum += __shfl_xor_sync(~0u, sum, o);
        float inv = 1.f / sum;
        for (int k = lane; k < S_; k += 32) row[k] *= inv;
    }
    __syncthreads();

    // ---- write att (coalesced) ----
    {
        float* abase = att + ((size_t)(b * H_ + h) * S_ + q0) * S_;
        for (int idx = tid; idx < QT * S_; idx += 256)
            abase[(size_t)(idx >> 10) * S_ + (idx & 1023)] = sc[(idx >> 10) * SCSTR + (idx & 1023)];
    }

    // ---- ctx = P @ V ----
    float acc3[4] = {0.f, 0.f, 0.f, 0.f};
    for (int c = 0; c < 8; c++) {
        __syncthreads();
        // load V chunk [128 x 64] -> kv (tf32)
#pragma unroll
        for (int i = 0; i < 8; i++) {
            int v = tid + 256 * i;
            int row = v >> 4, col = (v & 15) * 4;
            float4 t = *(const float4*)(g_qkv +
                (size_t)(b * S_ + c * KVT + row) * QKVN + h * 192 + 128 + col);
            t.x = to_tf32(t.x); t.y = to_tf32(t.y); t.z = to_tf32(t.z); t.w = to_tf32(t.w);
            *(float4*)(kv + row * KVSTR + col) = t;
        }
        __syncthreads();

#pragma unroll
        for (int ks = 0; ks < 16; ks++) {
            int kl = ks * 8;                 // chunk-local k offset
            int kg = c * 128 + kl;           // global
            uint32_t af[4], bf[2];
            af[0] = __float_as_uint(to_tf32(sc[(g)     * SCSTR + kg + a]));
            af[1] = __float_as_uint(to_tf32(sc[(g + 8) * SCSTR + kg + a]));
            af[2] = __float_as_uint(to_tf32(sc[(g)     * SCSTR + kg + 4 + a]));
            af[3] = __float_as_uint(to_tf32(sc[(g + 8) * SCSTR + kg + 4 + a]));
            bf[0] = __float_as_uint(kv[(kl + a)     * KVSTR + w * 8 + g]);
            bf[1] = __float_as_uint(kv[(kl + 4 + a) * KVSTR + w * 8 + g]);
            mma_tf32(acc3, af, bf);
        }
    }
    // write ctx: warp w owns dims [w*8, w*8+8)
    {
        int d = w * 8 + a * 2;
        int row0 = b * S_ + q0 + g;
        *(float2*)(g_ctx + (size_t)row0 * D_ + h * HD_ + d) =
            make_float2(acc3[0], acc3[1]);
        *(float2*)(g_ctx + (size_t)(row0 + 8) * D_ + h * HD_ + d) =
            make_float2(acc3[2], acc3[3]);
    }
}

// ---------------------------------------------------------------------------
extern "C" void kernel_launch(void* const* d_in, const int* in_sizes, int n_in,
                              void* d_out, int out_size)
{
    const float* x    = (const float*)d_in[0];
    const float* mask = (const float*)d_in[1];
    const float* Wqkv = (const float*)d_in[2];
    const float* bqkv = (const float*)d_in[3];
    const float* Wo   = (const float*)d_in[4];
    const float* bo   = (const float*)d_in[5];

    float* out = (float*)d_out;                       // [B,S,D]
    float* att = out + (size_t)B_ * S_ * D_;          // [B,H,S,S]

    cudaFuncSetAttribute(attn_kernel,
                         cudaFuncAttributeMaxDynamicSharedMemorySize, ATTN_SMEM);

    // 1) fused QKV projection (tf32 tensor cores)
    {
        dim3 grid(QKVN / 128, M_ / 128);
        qkv_gemm_kernel<<<grid, 256>>>(x, Wqkv, bqkv);
    }
    // 2) fused attention (scores + softmax + att write + ctx), tensor cores
    {
        dim3 grid(S_ / QT, H_, B_);
        attn_kernel<<<grid, 256, ATTN_SMEM>>>(mask, att);
    }
    // 3) output projection
    {
        dim3 grid(D_ / 128, M_ / 128);
        out_gemm_kernel<<<grid, 256>>>(Wo, bo, out);
    }
}

// round 4
// speedup vs baseline: 3.6601x; 1.1442x over previous
#include <cuda_runtime.h>
#include <cstdint>

// Problem constants
#define B_   4
#define S_   1024
#define D_   1024
#define H_   16
#define HD_  64
#define QKVN 3072
#define M_   (B_ * S_)

// Scratch (static device globals — allocation-free per harness rules)
__device__ float g_qkv[(size_t)M_ * QKVN];   // [b,s, h*192 + {q,k,v}*64]
__device__ float g_ctx[(size_t)M_ * D_];     // [b,s, h*64+d]

// ---------------------------------------------------------------------------
// helpers
// ---------------------------------------------------------------------------
__device__ __forceinline__ float to_tf32(float x) {
    uint32_t u;
    asm("cvt.rna.tf32.f32 %0, %1;" : "=r"(u) : "f"(x));
    return __uint_as_float(u);
}

__device__ __forceinline__ void mma_tf32(float* d, const uint32_t* a, const uint32_t* b) {
    asm volatile(
        "mma.sync.aligned.m16n8k8.row.col.f32.tf32.tf32.f32 "
        "{%0,%1,%2,%3}, {%4,%5,%6,%7}, {%8,%9}, {%0,%1,%2,%3};\n"
        : "+f"(d[0]), "+f"(d[1]), "+f"(d[2]), "+f"(d[3])
        : "r"(a[0]), "r"(a[1]), "r"(a[2]), "r"(a[3]), "r"(b[0]), "r"(b[1]));
}

// ---------------------------------------------------------------------------
// tf32 GEMM: C[M x N] = A[M x K] @ Bm[K x N] + bias[N]   (unchanged from R3)
// ---------------------------------------------------------------------------
#define BK   32
#define ASTR 36
#define BSTR 136

__device__ __forceinline__ void gemm_tf32_body(
    const float* __restrict__ A, const float* __restrict__ Bm,
    const float* __restrict__ bias, float* __restrict__ C,
    int N, int K)
{
    __shared__ float As[128 * ASTR];
    __shared__ float Bs[BK * BSTR];

    const int tid  = threadIdx.x;
    const int lane = tid & 31;
    const int wid  = tid >> 5;
    const int wm   = (wid & 3) * 32;
    const int wn   = (wid >> 2) * 64;
    const int bx   = blockIdx.x * 128;
    const int by   = blockIdx.y * 128;

    const int g = lane >> 2;
    const int a = lane & 3;

    float acc[2][8][4];
#pragma unroll
    for (int i = 0; i < 2; i++)
#pragma unroll
        for (int j = 0; j < 8; j++)
#pragma unroll
            for (int v = 0; v < 4; v++) acc[i][j][v] = 0.f;

    const int arow0 = tid >> 3;
    const int acol  = (tid & 7) * 4;
    const int brow0 = tid >> 5;
    const int bcol  = (tid & 31) * 4;

    for (int k0 = 0; k0 < K; k0 += BK) {
        float4 av[4], bv[4];
#pragma unroll
        for (int i = 0; i < 4; i++)
            av[i] = *(const float4*)(A + (size_t)(by + arow0 + 32 * i) * K + k0 + acol);
#pragma unroll
        for (int i = 0; i < 4; i++)
            bv[i] = *(const float4*)(Bm + (size_t)(k0 + brow0 + 8 * i) * N + bx + bcol);

        __syncthreads();
#pragma unroll
        for (int i = 0; i < 4; i++) {
            float4 t = av[i];
            t.x = to_tf32(t.x); t.y = to_tf32(t.y); t.z = to_tf32(t.z); t.w = to_tf32(t.w);
            *(float4*)(As + (arow0 + 32 * i) * ASTR + acol) = t;
        }
#pragma unroll
        for (int i = 0; i < 4; i++) {
            float4 t = bv[i];
            t.x = to_tf32(t.x); t.y = to_tf32(t.y); t.z = to_tf32(t.z); t.w = to_tf32(t.w);
            *(float4*)(Bs + (brow0 + 8 * i) * BSTR + bcol) = t;
        }
        __syncthreads();

#pragma unroll
        for (int kk = 0; kk < BK; kk += 8) {
            uint32_t af[2][4], bf[8][2];
#pragma unroll
            for (int i = 0; i < 2; i++) {
                int r = wm + i * 16 + g;
                af[i][0] = __float_as_uint(As[(r)     * ASTR + kk + a]);
                af[i][1] = __float_as_uint(As[(r + 8) * ASTR + kk + a]);
                af[i][2] = __float_as_uint(As[(r)     * ASTR + kk + 4 + a]);
                af[i][3] = __float_as_uint(As[(r + 8) * ASTR + kk + 4 + a]);
            }
#pragma unroll
            for (int j = 0; j < 8; j++) {
                int n = wn + j * 8 + g;
                bf[j][0] = __float_as_uint(Bs[(kk + a)     * BSTR + n]);
                bf[j][1] = __float_as_uint(Bs[(kk + 4 + a) * BSTR + n]);
            }
#pragma unroll
            for (int i = 0; i < 2; i++)
#pragma unroll
                for (int j = 0; j < 8; j++)
                    mma_tf32(acc[i][j], af[i], bf[j]);
        }
    }

#pragma unroll
    for (int i = 0; i < 2; i++) {
        int row = by + wm + i * 16 + g;
#pragma unroll
        for (int j = 0; j < 8; j++) {
            int col = bx + wn + j * 8 + a * 2;
            float b0 = bias[col], b1 = bias[col + 1];
            *(float2*)(C + (size_t)row * N + col) =
                make_float2(acc[i][j][0] + b0, acc[i][j][1] + b1);
            *(float2*)(C + (size_t)(row + 8) * N + col) =
                make_float2(acc[i][j][2] + b0, acc[i][j][3] + b1);
        }
    }
}

__global__ __launch_bounds__(256) void qkv_gemm_kernel(
    const float* __restrict__ x, const float* __restrict__ W,
    const float* __restrict__ bias)
{
    gemm_tf32_body(x, W, bias, g_qkv, QKVN, D_);
}

__global__ __launch_bounds__(256) void out_gemm_kernel(
    const float* __restrict__ W, const float* __restrict__ bias,
    float* __restrict__ out)
{
    gemm_tf32_body(g_ctx, W, bias, out, D_, D_);
}

// ---------------------------------------------------------------------------
// Fused attention, QT=32, 512 threads (16 warps), register-prefetch pipeline.
// sc[32][1028] fp32 scores; qs[32][68] tf32 Q; kv[128][72] tf32 K/V tile.
// Score phase: warp w -> rows (w>>3)*16..+16, cols (w&7)*16 of each 128-chunk.
// Ctx phase:   warp w -> rows (w>>3)*16..+16, head dims (w&7)*8..+8.
// ---------------------------------------------------------------------------
#define QT     32
#define KVT    128
#define SCSTR  1028
#define QSTR   68
#define KVSTR  72
#define NTHR   512
#define ATTN_SMEM ((QT * SCSTR + QT * QSTR + KVT * KVSTR) * 4)

__global__ __launch_bounds__(NTHR) void attn_kernel(
    const float* __restrict__ mask, float* __restrict__ att)
{
    extern __shared__ float sm[];
    float* sc = sm;                      // [QT][SCSTR]
    float* qs = sc + QT * SCSTR;         // [QT][QSTR]
    float* kv = qs + QT * QSTR;          // [KVT][KVSTR]

    const int b    = blockIdx.z;
    const int h    = blockIdx.y;
    const int q0   = blockIdx.x * QT;
    const int tid  = threadIdx.x;
    const int lane = tid & 31;
    const int w    = tid >> 5;
    const int g = lane >> 2;
    const int a = lane & 3;
    const int rbase = (w >> 3) * 16;     // 0 or 16
    const int cg    = (w & 7);           // 0..7

    // per-thread K/V chunk load geometry: 128x64 floats, 4x float4 each
    const int ldrow = tid >> 4;          // 0..31 (+32*i)
    const int ldcol = (tid & 15) * 4;

    // load Q tile (pre-scaled, tf32)
    for (int idx = tid; idx < QT * HD_; idx += NTHR) {
        int qi = idx >> 6, d = idx & 63;
        qs[qi * QSTR + d] =
            to_tf32(g_qkv[(size_t)(b * S_ + q0 + qi) * QKVN + h * 192 + d] * 0.125f);
    }

    float4 pf[4];
    // prefetch K chunk 0
#pragma unroll
    for (int i = 0; i < 4; i++)
        pf[i] = *(const float4*)(g_qkv +
            (size_t)(b * S_ + ldrow + 32 * i) * QKVN + h * 192 + 64 + ldcol);

    // ---- scores ----
    for (int c = 0; c < 8; c++) {
        __syncthreads();   // all warps done with previous kv tile
#pragma unroll
        for (int i = 0; i < 4; i++) {
            float4 t = pf[i];
            t.x = to_tf32(t.x); t.y = to_tf32(t.y); t.z = to_tf32(t.z); t.w = to_tf32(t.w);
            *(float4*)(kv + (ldrow + 32 * i) * KVSTR + ldcol) = t;
        }
        __syncthreads();
        if (c < 7) {       // prefetch next K chunk while computing
#pragma unroll
            for (int i = 0; i < 4; i++)
                pf[i] = *(const float4*)(g_qkv +
                    (size_t)(b * S_ + (c + 1) * KVT + ldrow + 32 * i) * QKVN + h * 192 + 64 + ldcol);
        }

        float acc2[2][4] = {{0.f,0.f,0.f,0.f},{0.f,0.f,0.f,0.f}};
#pragma unroll
        for (int ks = 0; ks < 8; ks++) {
            int k0 = ks * 8;
            uint32_t af[4], bf[2][2];
            af[0] = __float_as_uint(qs[(rbase + g)     * QSTR + k0 + a]);
            af[1] = __float_as_uint(qs[(rbase + g + 8) * QSTR + k0 + a]);
            af[2] = __float_as_uint(qs[(rbase + g)     * QSTR + k0 + 4 + a]);
            af[3] = __float_as_uint(qs[(rbase + g + 8) * QSTR + k0 + 4 + a]);
#pragma unroll
            for (int j = 0; j < 2; j++) {
                int n = cg * 16 + j * 8 + g;         // chunk-local kv row
                bf[j][0] = __float_as_uint(kv[n * KVSTR + k0 + a]);
                bf[j][1] = __float_as_uint(kv[n * KVSTR + k0 + 4 + a]);
            }
            mma_tf32(acc2[0], af, bf[0]);
            mma_tf32(acc2[1], af, bf[1]);
        }
        // write scores + mask into sc
#pragma unroll
        for (int j = 0; j < 2; j++) {
            int colG = c * 128 + cg * 16 + j * 8 + a * 2;
            const float* m0 = mask + ((size_t)(b * S_) + (q0 + rbase + g)) * S_ + colG;
            const float* m1 = mask + ((size_t)(b * S_) + (q0 + rbase + g + 8)) * S_ + colG;
            sc[(rbase + g)     * SCSTR + colG]     = acc2[j][0] + m0[0];
            sc[(rbase + g)     * SCSTR + colG + 1] = acc2[j][1] + m0[1];
            sc[(rbase + g + 8) * SCSTR + colG]     = acc2[j][2] + m1[0];
            sc[(rbase + g + 8) * SCSTR + colG + 1] = acc2[j][3] + m1[1];
        }
    }
    __syncthreads();

    // ---- softmax: one warp per 2 rows ----
    for (int r = w; r < QT; r += 16) {
        float* row = sc + r * SCSTR;
        float m = -1e30f;
        for (int k = lane; k < S_; k += 32) m = fmaxf(m, row[k]);
#pragma unroll
        for (int o = 16; o; o >>= 1) m = fmaxf(m, __shfl_xor_sync(~0u, m, o));
        float sum = 0.f;
        for (int k = lane; k < S_; k += 32) {
            float e = __expf(row[k] - m);
            row[k] = e;
            sum += e;
        }
#pragma unroll
        for (int o = 16; o; o >>= 1) sum += __shfl_xor_sync(~0u, sum, o);
        float inv = 1.f / sum;
        for (int k = lane; k < S_; k += 32) row[k] *= inv;
    }
    __syncthreads();

    // ---- write att (coalesced) ----
    {
        float* abase = att + ((size_t)(b * H_ + h) * S_ + q0) * S_;
        for (int idx = tid; idx < QT * S_; idx += NTHR)
            abase[(size_t)(idx >> 10) * S_ + (idx & 1023)] =
                sc[(idx >> 10) * SCSTR + (idx & 1023)];
    }

    // ---- ctx = P @ V ----
    const int dg = (w & 7) * 8;          // head-dim fragment for this warp
    float acc3[4] = {0.f, 0.f, 0.f, 0.f};

    // prefetch V chunk 0
#pragma unroll
    for (int i = 0; i < 4; i++)
        pf[i] = *(const float4*)(g_qkv +
            (size_t)(b * S_ + ldrow + 32 * i) * QKVN + h * 192 + 128 + ldcol);

    for (int c = 0; c < 8; c++) {
        __syncthreads();
#pragma unroll
        for (int i = 0; i < 4; i++) {
            float4 t = pf[i];
            t.x = to_tf32(t.x); t.y = to_tf32(t.y); t.z = to_tf32(t.z); t.w = to_tf32(t.w);
            *(float4*)(kv + (ldrow + 32 * i) * KVSTR + ldcol) = t;
        }
        __syncthreads();
        if (c < 7) {
#pragma unroll
            for (int i = 0; i < 4; i++)
                pf[i] = *(const float4*)(g_qkv +
                    (size_t)(b * S_ + (c + 1) * KVT + ldrow + 32 * i) * QKVN + h * 192 + 128 + ldcol);
        }

#pragma unroll
        for (int ks = 0; ks < 16; ks++) {
            int kl = ks * 8;
            int kg = c * 128 + kl;
            uint32_t af[4], bf[2];
            af[0] = __float_as_uint(to_tf32(sc[(rbase + g)     * SCSTR + kg + a]));
            af[1] = __float_as_uint(to_tf32(sc[(rbase + g + 8) * SCSTR + kg + a]));
            af[2] = __float_as_uint(to_tf32(sc[(rbase + g)     * SCSTR + kg + 4 + a]));
            af[3] = __float_as_uint(to_tf32(sc[(rbase + g + 8) * SCSTR + kg + 4 + a]));
            bf[0] = __float_as_uint(kv[(kl + a)     * KVSTR + dg + g]);
            bf[1] = __float_as_uint(kv[(kl + 4 + a) * KVSTR + dg + g]);
            mma_tf32(acc3, af, bf);
        }
    }
    // write ctx: warp w owns dims [dg, dg+8) for rows rbase..rbase+16
    {
        int d = dg + a * 2;
        int row0 = b * S_ + q0 + rbase + g;
        *(float2*)(g_ctx + (size_t)row0 * D_ + h * HD_ + d) =
            make_float2(acc3[0], acc3[1]);
        *(float2*)(g_ctx + (size_t)(row0 + 8) * D_ + h * HD_ + d) =
            make_float2(acc3[2], acc3[3]);
    }
}

// ---------------------------------------------------------------------------
extern "C" void kernel_launch(void* const* d_in, const int* in_sizes, int n_in,
                              void* d_out, int out_size)
{
    const float* x    = (const float*)d_in[0];
    const float* mask = (const float*)d_in[1];
    const float* Wqkv = (const float*)d_in[2];
    const float* bqkv = (const float*)d_in[3];
    const float* Wo   = (const float*)d_in[4];
    const float* bo   = (const float*)d_in[5];

    float* out = (float*)d_out;                       // [B,S,D]
    float* att = out + (size_t)B_ * S_ * D_;          // [B,H,S,S]

    cudaFuncSetAttribute(attn_kernel,
                         cudaFuncAttributeMaxDynamicSharedMemorySize, ATTN_SMEM);

    // 1) fused QKV projection (tf32 tensor cores)
    {
        dim3 grid(QKVN / 128, M_ / 128);
        qkv_gemm_kernel<<<grid, 256>>>(x, Wqkv, bqkv);
    }
    // 2) fused attention (scores + softmax + att write + ctx), tensor cores
    {
        dim3 grid(S_ / QT, H_, B_);
        attn_kernel<<<grid, NTHR, ATTN_SMEM>>>(mask, att);
    }
    // 3) output projection
    {
        dim3 grid(D_ / 128, M_ / 128);
        out_gemm_kernel<<<grid, 256>>>(Wo, bo, out);
    }
}

// round 5
// speedup vs baseline: 3.8198x; 1.0436x over previous
#include <cuda_runtime.h>
#include <cstdint>

// Problem constants
#define B_   4
#define S_   1024
#define D_   1024
#define H_   16
#define HD_  64
#define QKVN 3072
#define M_   (B_ * S_)

// Scratch (static device globals — allocation-free per harness rules)
__device__ float g_qkv[(size_t)M_ * QKVN];   // [b,s, h*192 + {q,k,v}*64]
__device__ float g_ctx[(size_t)M_ * D_];     // [b,s, h*64+d]

// ---------------------------------------------------------------------------
// helpers
// ---------------------------------------------------------------------------
__device__ __forceinline__ float to_tf32(float x) {
    uint32_t u;
    asm("cvt.rna.tf32.f32 %0, %1;" : "=r"(u) : "f"(x));
    return __uint_as_float(u);
}

__device__ __forceinline__ void mma_tf32(float* d, const uint32_t* a, const uint32_t* b) {
    asm volatile(
        "mma.sync.aligned.m16n8k8.row.col.f32.tf32.tf32.f32 "
        "{%0,%1,%2,%3}, {%4,%5,%6,%7}, {%8,%9}, {%0,%1,%2,%3};\n"
        : "+f"(d[0]), "+f"(d[1]), "+f"(d[2]), "+f"(d[3])
        : "r"(a[0]), "r"(a[1]), "r"(a[2]), "r"(a[3]), "r"(b[0]), "r"(b[1]));
}

// ---------------------------------------------------------------------------
// tf32 GEMM, double-buffered smem, one sync per K-tile.
// C[M x N] = A[M x K] @ Bm[K x N] + bias[N]
// 128x128 block tile, BK=32, 8 warps (4x2), warp tile 32x64.
// As stride 36 (CF: bank 4g+a), Bs stride 136 (CF: 8a+g).
// ---------------------------------------------------------------------------
#define BK   32
#define ASTR 36
#define BSTR 136
#define ATILE (128 * ASTR)
#define BTILE (BK * BSTR)
#define GEMM_SMEM (2 * (ATILE + BTILE) * 4)

__device__ __forceinline__ void gemm_tf32_body(
    const float* __restrict__ A, const float* __restrict__ Bm,
    const float* __restrict__ bias, float* __restrict__ C,
    int N, int K, bool round_out)
{
    extern __shared__ float smg[];
    float* As = smg;              // [2][ATILE]
    float* Bs = smg + 2 * ATILE;  // [2][BTILE]

    const int tid  = threadIdx.x;
    const int lane = tid & 31;
    const int wid  = tid >> 5;
    const int wm   = (wid & 3) * 32;
    const int wn   = (wid >> 2) * 64;
    const int bx   = blockIdx.x * 128;
    const int by   = blockIdx.y * 128;

    const int g = lane >> 2;
    const int a = lane & 3;

    float acc[2][8][4];
#pragma unroll
    for (int i = 0; i < 2; i++)
#pragma unroll
        for (int j = 0; j < 8; j++)
#pragma unroll
            for (int v = 0; v < 4; v++) acc[i][j][v] = 0.f;

    const int arow0 = tid >> 3;
    const int acol  = (tid & 7) * 4;
    const int brow0 = tid >> 5;
    const int bcol  = (tid & 31) * 4;

    float4 av[4], bv[4];

#define G_LOAD(k0)                                                              \
    {                                                                           \
        _Pragma("unroll")                                                       \
        for (int i = 0; i < 4; i++)                                             \
            av[i] = *(const float4*)(A + (size_t)(by + arow0 + 32 * i) * K + (k0) + acol); \
        _Pragma("unroll")                                                       \
        for (int i = 0; i < 4; i++)                                             \
            bv[i] = *(const float4*)(Bm + (size_t)((k0) + brow0 + 8 * i) * N + bx + bcol); \
    }

#define G_STORE(buf)                                                            \
    {                                                                           \
        float* Ad = As + (buf) * ATILE;                                         \
        float* Bd = Bs + (buf) * BTILE;                                         \
        _Pragma("unroll")                                                       \
        for (int i = 0; i < 4; i++) {                                           \
            float4 t = av[i];                                                   \
            t.x = to_tf32(t.x); t.y = to_tf32(t.y);                             \
            t.z = to_tf32(t.z); t.w = to_tf32(t.w);                             \
            *(float4*)(Ad + (arow0 + 32 * i) * ASTR + acol) = t;                \
        }                                                                       \
        _Pragma("unroll")                                                       \
        for (int i = 0; i < 4; i++) {                                           \
            float4 t = bv[i];                                                   \
            t.x = to_tf32(t.x); t.y = to_tf32(t.y);                             \
            t.z = to_tf32(t.z); t.w = to_tf32(t.w);                             \
            *(float4*)(Bd + (brow0 + 8 * i) * BSTR + bcol) = t;                 \
        }                                                                       \
    }

    const int nk = K / BK;
    // prologue
    G_LOAD(0);
    G_STORE(0);
    G_LOAD(BK);
    __syncthreads();

    for (int it = 0; it < nk; it++) {
        const float* Ab_ = As + (it & 1) * ATILE;
        const float* Bb_ = Bs + (it & 1) * BTILE;
        if (it + 1 < nk) G_STORE((it + 1) & 1);
        if (it + 2 < nk) G_LOAD((it + 2) * BK);

#pragma unroll
        for (int kk = 0; kk < BK; kk += 8) {
            uint32_t af[2][4], bf[8][2];
#pragma unroll
            for (int i = 0; i < 2; i++) {
                int r = wm + i * 16 + g;
                af[i][0] = __float_as_uint(Ab_[(r)     * ASTR + kk + a]);
                af[i][1] = __float_as_uint(Ab_[(r + 8) * ASTR + kk + a]);
                af[i][2] = __float_as_uint(Ab_[(r)     * ASTR + kk + 4 + a]);
                af[i][3] = __float_as_uint(Ab_[(r + 8) * ASTR + kk + 4 + a]);
            }
#pragma unroll
            for (int j = 0; j < 8; j++) {
                int n = wn + j * 8 + g;
                bf[j][0] = __float_as_uint(Bb_[(kk + a)     * BSTR + n]);
                bf[j][1] = __float_as_uint(Bb_[(kk + 4 + a) * BSTR + n]);
            }
#pragma unroll
            for (int i = 0; i < 2; i++)
#pragma unroll
                for (int j = 0; j < 8; j++)
                    mma_tf32(acc[i][j], af[i], bf[j]);
        }
        __syncthreads();
    }
#undef G_LOAD
#undef G_STORE

#pragma unroll
    for (int i = 0; i < 2; i++) {
        int row = by + wm + i * 16 + g;
#pragma unroll
        for (int j = 0; j < 8; j++) {
            int col = bx + wn + j * 8 + a * 2;
            float b0 = bias[col], b1 = bias[col + 1];
            float4 r;
            r.x = acc[i][j][0] + b0; r.y = acc[i][j][1] + b1;
            r.z = acc[i][j][2] + b0; r.w = acc[i][j][3] + b1;
            if (round_out) {   // pre-round values consumed later as tf32
                r.x = to_tf32(r.x); r.y = to_tf32(r.y);
                r.z = to_tf32(r.z); r.w = to_tf32(r.w);
            }
            *(float2*)(C + (size_t)row * N + col)       = make_float2(r.x, r.y);
            *(float2*)(C + (size_t)(row + 8) * N + col) = make_float2(r.z, r.w);
        }
    }
}

__global__ __launch_bounds__(256, 2) void qkv_gemm_kernel(
    const float* __restrict__ x, const float* __restrict__ W,
    const float* __restrict__ bias)
{
    gemm_tf32_body(x, W, bias, g_qkv, QKVN, D_, false);
}

__global__ __launch_bounds__(256, 2) void out_gemm_kernel(
    const float* __restrict__ W, const float* __restrict__ bias,
    float* __restrict__ out)
{
    gemm_tf32_body(g_ctx, W, bias, out, D_, D_, false);
}

// ---------------------------------------------------------------------------
// Fused attention, QT=32, 512 threads (16 warps).
// Double-buffered kv tile, hoisted Q fragments, mask prefetch, 1 sync/chunk.
// sc[32][1028] fp32 scores; qs[32][68] tf32 Q; kv[2][128][72] tf32 K/V.
// Score phase: warp w -> rows (w>>3)*16..+16, cols (w&7)*16 of each 128-chunk.
// Ctx phase:   warp w -> rows (w>>3)*16..+16, head dims (w&7)*8..+8.
// ---------------------------------------------------------------------------
#define QT     32
#define KVT    128
#define SCSTR  1028
#define QSTR   68
#define KVSTR  72
#define KVTILE (KVT * KVSTR)
#define NTHR   512
#define ATTN_SMEM ((QT * SCSTR + QT * QSTR + 2 * KVTILE) * 4)

__global__ __launch_bounds__(NTHR) void attn_kernel(
    const float* __restrict__ mask, float* __restrict__ att)
{
    extern __shared__ float sm[];
    float* sc = sm;                      // [QT][SCSTR]
    float* qs = sc + QT * SCSTR;         // [QT][QSTR]
    float* kv = qs + QT * QSTR;          // [2][KVT][KVSTR]

    const int b    = blockIdx.z;
    const int h    = blockIdx.y;
    const int q0   = blockIdx.x * QT;
    const int tid  = threadIdx.x;
    const int lane = tid & 31;
    const int w    = tid >> 5;
    const int g = lane >> 2;
    const int a = lane & 3;
    const int rbase = (w >> 3) * 16;     // 0 or 16
    const int cg    = (w & 7);           // 0..7

    const int ldrow = tid >> 4;          // 0..31 (+32*i)
    const int ldcol = (tid & 15) * 4;

    const float* qkv_b = g_qkv + (size_t)(b * S_) * QKVN + h * 192;

    float4 pf[4];
    float2 mreg[2][2], mnext[2][2];

#define KV_LDG(off, c)                                                         \
    {                                                                          \
        _Pragma("unroll")                                                      \
        for (int i = 0; i < 4; i++)                                            \
            pf[i] = *(const float4*)(qkv_b +                                   \
                (size_t)((c) * KVT + ldrow + 32 * i) * QKVN + (off) + ldcol);  \
    }
#define KV_STS(buf)                                                            \
    {                                                                          \
        float* dst = kv + (buf) * KVTILE;                                      \
        _Pragma("unroll")                                                      \
        for (int i = 0; i < 4; i++) {                                          \
            float4 t = pf[i];                                                  \
            t.x = to_tf32(t.x); t.y = to_tf32(t.y);                            \
            t.z = to_tf32(t.z); t.w = to_tf32(t.w);                            \
            *(float4*)(dst + (ldrow + 32 * i) * KVSTR + ldcol) = t;            \
        }                                                                      \
    }
#define MASK_LDG(dst, c)                                                       \
    {                                                                          \
        const float* mp = mask + ((size_t)(b * S_) + (q0 + rbase + g)) * S_    \
                          + (c) * 128 + cg * 16 + a * 2;                       \
        dst[0][0] = *(const float2*)(mp);                                      \
        dst[0][1] = *(const float2*)(mp + 8);                                  \
        mp += (size_t)8 * S_;                                                  \
        dst[1][0] = *(const float2*)(mp);                                      \
        dst[1][1] = *(const float2*)(mp + 8);                                  \
    }

    // ---- prologue: Q tile, K chunk 0, mask chunk 0 ----
    for (int idx = tid; idx < QT * HD_; idx += NTHR) {
        int qi = idx >> 6, d = idx & 63;
        qs[qi * QSTR + d] = to_tf32(qkv_b[(size_t)(q0 + qi) * QKVN + d] * 0.125f);
    }
    KV_LDG(64, 0);
    KV_STS(0);
    KV_LDG(64, 1);
    MASK_LDG(mreg, 0);
    __syncthreads();    // qs + kv[0] visible

    // hoist Q fragments (invariant over chunks)
    uint32_t afq[8][4];
#pragma unroll
    for (int ks = 0; ks < 8; ks++) {
        int k0 = ks * 8;
        afq[ks][0] = __float_as_uint(qs[(rbase + g)     * QSTR + k0 + a]);
        afq[ks][1] = __float_as_uint(qs[(rbase + g + 8) * QSTR + k0 + a]);
        afq[ks][2] = __float_as_uint(qs[(rbase + g)     * QSTR + k0 + 4 + a]);
        afq[ks][3] = __float_as_uint(qs[(rbase + g + 8) * QSTR + k0 + 4 + a]);
    }

    // ---- scores: 1 sync per chunk ----
    for (int c = 0; c < 8; c++) {
        const float* kvc = kv + (c & 1) * KVTILE;
        if (c < 7) KV_STS((c + 1) & 1);         // stage K[c+1] (regs -> smem)
        if (c < 6) KV_LDG(64, c + 2);           // prefetch K[c+2]
        if (c < 7) MASK_LDG(mnext, c + 1);      // prefetch mask[c+1]

        float acc2[2][4] = {{0.f,0.f,0.f,0.f},{0.f,0.f,0.f,0.f}};
#pragma unroll
        for (int ks = 0; ks < 8; ks++) {
            int k0 = ks * 8;
            uint32_t bf[2][2];
#pragma unroll
            for (int j = 0; j < 2; j++) {
                int n = cg * 16 + j * 8 + g;
                bf[j][0] = __float_as_uint(kvc[n * KVSTR + k0 + a]);
                bf[j][1] = __float_as_uint(kvc[n * KVSTR + k0 + 4 + a]);
            }
            mma_tf32(acc2[0], afq[ks], bf[0]);
            mma_tf32(acc2[1], afq[ks], bf[1]);
        }
#pragma unroll
        for (int j = 0; j < 2; j++) {
            int colG = c * 128 + cg * 16 + j * 8 + a * 2;
            sc[(rbase + g)     * SCSTR + colG]     = acc2[j][0] + mreg[0][j].x;
            sc[(rbase + g)     * SCSTR + colG + 1] = acc2[j][1] + mreg[0][j].y;
            sc[(rbase + g + 8) * SCSTR + colG]     = acc2[j][2] + mreg[1][j].x;
            sc[(rbase + g + 8) * SCSTR + colG + 1] = acc2[j][3] + mreg[1][j].y;
        }
#pragma unroll
        for (int i = 0; i < 2; i++)
#pragma unroll
            for (int j = 0; j < 2; j++) mreg[i][j] = mnext[i][j];
        __syncthreads();
    }

    // prefetch V chunk 0 (overlaps softmax + att write)
    KV_LDG(128, 0);

    // ---- softmax: one warp per 2 rows ----
    for (int r = w; r < QT; r += 16) {
        float* row = sc + r * SCSTR;
        float m = -1e30f;
        for (int k = lane; k < S_; k += 32) m = fmaxf(m, row[k]);
#pragma unroll
        for (int o = 16; o; o >>= 1) m = fmaxf(m, __shfl_xor_sync(~0u, m, o));
        float sum = 0.f;
        for (int k = lane; k < S_; k += 32) {
            float e = __expf(row[k] - m);
            row[k] = e;
            sum += e;
        }
#pragma unroll
        for (int o = 16; o; o >>= 1) sum += __shfl_xor_sync(~0u, sum, o);
        float inv = 1.f / sum;
        for (int k = lane; k < S_; k += 32) row[k] *= inv;
    }
    __syncthreads();

    // ---- write att (coalesced) + convert sc to tf32 in place ----
    {
        float* abase = att + ((size_t)(b * H_ + h) * S_ + q0) * S_;
        for (int idx = tid; idx < QT * S_; idx += NTHR) {
            int si = (idx >> 10) * SCSTR + (idx & 1023);
            float v = sc[si];
            abase[(size_t)(idx >> 10) * S_ + (idx & 1023)] = v;
            sc[si] = to_tf32(v);
        }
    }
    KV_STS(0);          // stage V[0] (kv buffers free after score loop)
    KV_LDG(128, 1);
    __syncthreads();    // sc(tf32) + kv[0](V) visible

    // ---- ctx = P @ V : 1 sync per chunk ----
    const int dg = (w & 7) * 8;
    float acc3[4] = {0.f, 0.f, 0.f, 0.f};
    for (int c = 0; c < 8; c++) {
        const float* kvc = kv + (c & 1) * KVTILE;
        if (c < 7) KV_STS((c + 1) & 1);
        if (c < 6) KV_LDG(128, c + 2);

#pragma unroll
        for (int ks = 0; ks < 16; ks++) {
            int kl = ks * 8;
            int kg = c * 128 + kl;
            uint32_t af[4], bf[2];
            af[0] = __float_as_uint(sc[(rbase + g)     * SCSTR + kg + a]);
            af[1] = __float_as_uint(sc[(rbase + g + 8) * SCSTR + kg + a]);
            af[2] = __float_as_uint(sc[(rbase + g)     * SCSTR + kg + 4 + a]);
            af[3] = __float_as_uint(sc[(rbase + g + 8) * SCSTR + kg + 4 + a]);
            bf[0] = __float_as_uint(kvc[(kl + a)     * KVSTR + dg + g]);
            bf[1] = __float_as_uint(kvc[(kl + 4 + a) * KVSTR + dg + g]);
            mma_tf32(acc3, af, bf);
        }
        __syncthreads();
    }
#undef KV_LDG
#undef KV_STS
#undef MASK_LDG

    // write ctx: warp w owns dims [dg, dg+8) for rows rbase..rbase+16
    {
        int d = dg + a * 2;
        int row0 = b * S_ + q0 + rbase + g;
        *(float2*)(g_ctx + (size_t)row0 * D_ + h * HD_ + d) =
            make_float2(acc3[0], acc3[1]);
        *(float2*)(g_ctx + (size_t)(row0 + 8) * D_ + h * HD_ + d) =
            make_float2(acc3[2], acc3[3]);
    }
}

// ---------------------------------------------------------------------------
extern "C" void kernel_launch(void* const* d_in, const int* in_sizes, int n_in,
                              void* d_out, int out_size)
{
    const float* x    = (const float*)d_in[0];
    const float* mask = (const float*)d_in[1];
    const float* Wqkv = (const float*)d_in[2];
    const float* bqkv = (const float*)d_in[3];
    const float* Wo   = (const float*)d_in[4];
    const float* bo   = (const float*)d_in[5];

    float* out = (float*)d_out;                       // [B,S,D]
    float* att = out + (size_t)B_ * S_ * D_;          // [B,H,S,S]

    cudaFuncSetAttribute(attn_kernel,
                         cudaFuncAttributeMaxDynamicSharedMemorySize, ATTN_SMEM);
    cudaFuncSetAttribute(qkv_gemm_kernel,
                         cudaFuncAttributeMaxDynamicSharedMemorySize, GEMM_SMEM);
    cudaFuncSetAttribute(out_gemm_kernel,
                         cudaFuncAttributeMaxDynamicSharedMemorySize, GEMM_SMEM);

    // 1) fused QKV projection (tf32 tensor cores)
    {
        dim3 grid(QKVN / 128, M_ / 128);
        qkv_gemm_kernel<<<grid, 256, GEMM_SMEM>>>(x, Wqkv, bqkv);
    }
    // 2) fused attention (scores + softmax + att write + ctx), tensor cores
    {
        dim3 grid(S_ / QT, H_, B_);
        attn_kernel<<<grid, NTHR, ATTN_SMEM>>>(mask, att);
    }
    // 3) output projection
    {
        dim3 grid(D_ / 128, M_ / 128);
        out_gemm_kernel<<<grid, 256, GEMM_SMEM>>>(Wo, bo, out);
    }
}

// round 6
// speedup vs baseline: 3.9252x; 1.0276x over previous
#include <cuda_runtime.h>
#include <cstdint>

// Problem constants
#define B_   4
#define S_   1024
#define D_   1024
#define H_   16
#define HD_  64
#define QKVN 3072
#define M_   (B_ * S_)

// Scratch (static device globals — allocation-free per harness rules)
__device__ float g_qkv[(size_t)M_ * QKVN];   // [b,s, h*192 + {q,k,v}*64]
__device__ float g_ctx[(size_t)M_ * D_];     // [b,s, h*64+d]

// ---------------------------------------------------------------------------
// helpers
// ---------------------------------------------------------------------------
__device__ __forceinline__ float to_tf32(float x) {
    uint32_t u;
    asm("cvt.rna.tf32.f32 %0, %1;" : "=r"(u) : "f"(x));
    return __uint_as_float(u);
}

__device__ __forceinline__ void mma_tf32(float* d, const uint32_t* a, const uint32_t* b) {
    asm volatile(
        "mma.sync.aligned.m16n8k8.row.col.f32.tf32.tf32.f32 "
        "{%0,%1,%2,%3}, {%4,%5,%6,%7}, {%8,%9}, {%0,%1,%2,%3};\n"
        : "+f"(d[0]), "+f"(d[1]), "+f"(d[2]), "+f"(d[3])
        : "r"(a[0]), "r"(a[1]), "r"(a[2]), "r"(a[3]), "r"(b[0]), "r"(b[1]));
}

// ---------------------------------------------------------------------------
// tf32 GEMM: block tile 256x128, BK=32, 8 warps (4 M x 2 N), warp tile 64x64.
// 128 B smem-read per MMA (A reused over 8 n-frags, B over 4 m-frags).
// As stride 36 (CF: bank 4g+a), Bs stride 136 (CF: 8a+8j+g).
// ---------------------------------------------------------------------------
#define BK   32
#define ASTR 36
#define BSTR 136
#define BM_T 256
#define ATILE (BM_T * ASTR)
#define BTILE (BK * BSTR)
#define GEMM_SMEM (2 * (ATILE + BTILE) * 4)

__device__ __forceinline__ void gemm_tf32_body(
    const float* __restrict__ A, const float* __restrict__ Bm,
    const float* __restrict__ bias, float* __restrict__ C,
    int N, int K)
{
    extern __shared__ float smg[];
    float* As = smg;              // [2][ATILE]
    float* Bs = smg + 2 * ATILE;  // [2][BTILE]

    const int tid  = threadIdx.x;
    const int lane = tid & 31;
    const int wid  = tid >> 5;
    const int wm   = (wid & 3) * 64;   // warp M offset (0,64,128,192)
    const int wn   = (wid >> 2) * 64;  // warp N offset (0,64)
    const int bx   = blockIdx.x * 128;
    const int by   = blockIdx.y * BM_T;

    const int g = lane >> 2;
    const int a = lane & 3;

    float acc[4][8][4];
#pragma unroll
    for (int i = 0; i < 4; i++)
#pragma unroll
        for (int j = 0; j < 8; j++)
#pragma unroll
            for (int v = 0; v < 4; v++) acc[i][j][v] = 0.f;

    const int arow0 = tid >> 3;          // 0..31 (+32*i, 8 iters)
    const int acol  = (tid & 7) * 4;
    const int brow0 = tid >> 5;          // 0..7 (+8*i, 4 iters)
    const int bcol  = (tid & 31) * 4;

    float4 av[8], bv[4];

#define G_LOAD(k0)                                                              \
    {                                                                           \
        _Pragma("unroll")                                                       \
        for (int i = 0; i < 8; i++)                                             \
            av[i] = *(const float4*)(A + (size_t)(by + arow0 + 32 * i) * K + (k0) + acol); \
        _Pragma("unroll")                                                       \
        for (int i = 0; i < 4; i++)                                             \
            bv[i] = *(const float4*)(Bm + (size_t)((k0) + brow0 + 8 * i) * N + bx + bcol); \
    }

#define G_STORE(buf)                                                            \
    {                                                                           \
        float* Ad = As + (buf) * ATILE;                                         \
        float* Bd = Bs + (buf) * BTILE;                                         \
        _Pragma("unroll")                                                       \
        for (int i = 0; i < 8; i++) {                                           \
            float4 t = av[i];                                                   \
            t.x = to_tf32(t.x); t.y = to_tf32(t.y);                             \
            t.z = to_tf32(t.z); t.w = to_tf32(t.w);                             \
            *(float4*)(Ad + (arow0 + 32 * i) * ASTR + acol) = t;                \
        }                                                                       \
        _Pragma("unroll")                                                       \
        for (int i = 0; i < 4; i++) {                                           \
            float4 t = bv[i];                                                   \
            t.x = to_tf32(t.x); t.y = to_tf32(t.y);                             \
            t.z = to_tf32(t.z); t.w = to_tf32(t.w);                             \
            *(float4*)(Bd + (brow0 + 8 * i) * BSTR + bcol) = t;                 \
        }                                                                       \
    }

    const int nk = K / BK;
    G_LOAD(0);
    G_STORE(0);
    G_LOAD(BK);
    __syncthreads();

    for (int it = 0; it < nk; it++) {
        const float* Ab_ = As + (it & 1) * ATILE;
        const float* Bb_ = Bs + (it & 1) * BTILE;
        if (it + 1 < nk) G_STORE((it + 1) & 1);
        if (it + 2 < nk) G_LOAD((it + 2) * BK);

#pragma unroll
        for (int kk = 0; kk < BK; kk += 8) {
            uint32_t af[4][4], bf[8][2];
#pragma unroll
            for (int i = 0; i < 4; i++) {
                int r = wm + i * 16 + g;
                af[i][0] = __float_as_uint(Ab_[(r)     * ASTR + kk + a]);
                af[i][1] = __float_as_uint(Ab_[(r + 8) * ASTR + kk + a]);
                af[i][2] = __float_as_uint(Ab_[(r)     * ASTR + kk + 4 + a]);
                af[i][3] = __float_as_uint(Ab_[(r + 8) * ASTR + kk + 4 + a]);
            }
#pragma unroll
            for (int j = 0; j < 8; j++) {
                int n = wn + j * 8 + g;
                bf[j][0] = __float_as_uint(Bb_[(kk + a)     * BSTR + n]);
                bf[j][1] = __float_as_uint(Bb_[(kk + 4 + a) * BSTR + n]);
            }
#pragma unroll
            for (int i = 0; i < 4; i++)
#pragma unroll
                for (int j = 0; j < 8; j++)
                    mma_tf32(acc[i][j], af[i], bf[j]);
        }
        __syncthreads();
    }
#undef G_LOAD
#undef G_STORE

#pragma unroll
    for (int i = 0; i < 4; i++) {
        int row = by + wm + i * 16 + g;
#pragma unroll
        for (int j = 0; j < 8; j++) {
            int col = bx + wn + j * 8 + a * 2;
            float b0 = bias[col], b1 = bias[col + 1];
            *(float2*)(C + (size_t)row * N + col) =
                make_float2(acc[i][j][0] + b0, acc[i][j][1] + b1);
            *(float2*)(C + (size_t)(row + 8) * N + col) =
                make_float2(acc[i][j][2] + b0, acc[i][j][3] + b1);
        }
    }
}

__global__ __launch_bounds__(256, 1) void qkv_gemm_kernel(
    const float* __restrict__ x, const float* __restrict__ W,
    const float* __restrict__ bias)
{
    gemm_tf32_body(x, W, bias, g_qkv, QKVN, D_);
}

__global__ __launch_bounds__(256, 1) void out_gemm_kernel(
    const float* __restrict__ W, const float* __restrict__ bias,
    float* __restrict__ out)
{
    gemm_tf32_body(g_ctx, W, bias, out, D_, D_);
}

// ---------------------------------------------------------------------------
// Fused attention, QT=32, 512 threads (16 warps).
// Score phase: warp w -> rows (w>>3)*16..+16, cols (w&7)*16 of each 128-chunk
//   (Q fragments hoisted in registers; 256 B/MMA).
// Ctx phase:   warp w -> rows (w>>3)*16..+16, ALL 64 head dims, k-slice
//   (w&7)*16..+16 of each 128-chunk (A reused over 8 n-frags; 320 B/MMA),
//   followed by an 8-way cross-warp reduction staged in the sc region.
// ---------------------------------------------------------------------------
#define QT     32
#define KVT    128
#define SCSTR  1028
#define QSTR   68
#define KVSTR  72
#define KVTILE (KVT * KVSTR)
#define NTHR   512
#define RSTR   68     // reduction staging row stride
#define ATTN_SMEM ((QT * SCSTR + QT * QSTR + 2 * KVTILE) * 4)

__global__ __launch_bounds__(NTHR) void attn_kernel(
    const float* __restrict__ mask, float* __restrict__ att)
{
    extern __shared__ float sm[];
    float* sc = sm;                      // [QT][SCSTR]
    float* qs = sc + QT * SCSTR;         // [QT][QSTR]
    float* kv = qs + QT * QSTR;          // [2][KVT][KVSTR]

    const int b    = blockIdx.z;
    const int h    = blockIdx.y;
    const int q0   = blockIdx.x * QT;
    const int tid  = threadIdx.x;
    const int lane = tid & 31;
    const int w    = tid >> 5;
    const int g = lane >> 2;
    const int a = lane & 3;
    const int rbase = (w >> 3) * 16;     // 0 or 16
    const int cg    = (w & 7);           // 0..7

    const int ldrow = tid >> 4;          // 0..31 (+32*i)
    const int ldcol = (tid & 15) * 4;

    const float* qkv_b = g_qkv + (size_t)(b * S_) * QKVN + h * 192;

    float4 pf[4];
    float2 mreg[2][2], mnext[2][2];

#define KV_LDG(off, c)                                                         \
    {                                                                          \
        _Pragma("unroll")                                                      \
        for (int i = 0; i < 4; i++)                                            \
            pf[i] = *(const float4*)(qkv_b +                                   \
                (size_t)((c) * KVT + ldrow + 32 * i) * QKVN + (off) + ldcol);  \
    }
#define KV_STS(buf)                                                            \
    {                                                                          \
        float* dst = kv + (buf) * KVTILE;                                      \
        _Pragma("unroll")                                                      \
        for (int i = 0; i < 4; i++) {                                          \
            float4 t = pf[i];                                                  \
            t.x = to_tf32(t.x); t.y = to_tf32(t.y);                            \
            t.z = to_tf32(t.z); t.w = to_tf32(t.w);                            \
            *(float4*)(dst + (ldrow + 32 * i) * KVSTR + ldcol) = t;            \
        }                                                                      \
    }
#define MASK_LDG(dst, c)                                                       \
    {                                                                          \
        const float* mp = mask + ((size_t)(b * S_) + (q0 + rbase + g)) * S_    \
                          + (c) * 128 + cg * 16 + a * 2;                       \
        dst[0][0] = *(const float2*)(mp);                                      \
        dst[0][1] = *(const float2*)(mp + 8);                                  \
        mp += (size_t)8 * S_;                                                  \
        dst[1][0] = *(const float2*)(mp);                                      \
        dst[1][1] = *(const float2*)(mp + 8);                                  \
    }

    // ---- prologue: Q tile, K chunk 0, mask chunk 0 ----
    for (int idx = tid; idx < QT * HD_; idx += NTHR) {
        int qi = idx >> 6, d = idx & 63;
        qs[qi * QSTR + d] = to_tf32(qkv_b[(size_t)(q0 + qi) * QKVN + d] * 0.125f);
    }
    KV_LDG(64, 0);
    KV_STS(0);
    KV_LDG(64, 1);
    MASK_LDG(mreg, 0);
    __syncthreads();

    // hoist Q fragments (invariant over chunks)
    uint32_t afq[8][4];
#pragma unroll
    for (int ks = 0; ks < 8; ks++) {
        int k0 = ks * 8;
        afq[ks][0] = __float_as_uint(qs[(rbase + g)     * QSTR + k0 + a]);
        afq[ks][1] = __float_as_uint(qs[(rbase + g + 8) * QSTR + k0 + a]);
        afq[ks][2] = __float_as_uint(qs[(rbase + g)     * QSTR + k0 + 4 + a]);
        afq[ks][3] = __float_as_uint(qs[(rbase + g + 8) * QSTR + k0 + 4 + a]);
    }

    // ---- scores: 1 sync per chunk ----
    for (int c = 0; c < 8; c++) {
        const float* kvc = kv + (c & 1) * KVTILE;
        if (c < 7) KV_STS((c + 1) & 1);
        if (c < 6) KV_LDG(64, c + 2);
        if (c < 7) MASK_LDG(mnext, c + 1);

        float acc2[2][4] = {{0.f,0.f,0.f,0.f},{0.f,0.f,0.f,0.f}};
#pragma unroll
        for (int ks = 0; ks < 8; ks++) {
            int k0 = ks * 8;
            uint32_t bf[2][2];
#pragma unroll
            for (int j = 0; j < 2; j++) {
                int n = cg * 16 + j * 8 + g;
                bf[j][0] = __float_as_uint(kvc[n * KVSTR + k0 + a]);
                bf[j][1] = __float_as_uint(kvc[n * KVSTR + k0 + 4 + a]);
            }
            mma_tf32(acc2[0], afq[ks], bf[0]);
            mma_tf32(acc2[1], afq[ks], bf[1]);
        }
#pragma unroll
        for (int j = 0; j < 2; j++) {
            int colG = c * 128 + cg * 16 + j * 8 + a * 2;
            sc[(rbase + g)     * SCSTR + colG]     = acc2[j][0] + mreg[0][j].x;
            sc[(rbase + g)     * SCSTR + colG + 1] = acc2[j][1] + mreg[0][j].y;
            sc[(rbase + g + 8) * SCSTR + colG]     = acc2[j][2] + mreg[1][j].x;
            sc[(rbase + g + 8) * SCSTR + colG + 1] = acc2[j][3] + mreg[1][j].y;
        }
#pragma unroll
        for (int i = 0; i < 2; i++)
#pragma unroll
            for (int j = 0; j < 2; j++) mreg[i][j] = mnext[i][j];
        __syncthreads();
    }

    // prefetch V chunk 0 (overlaps softmax + att write)
    KV_LDG(128, 0);

    // ---- softmax: one warp per 2 rows ----
    for (int r = w; r < QT; r += 16) {
        float* row = sc + r * SCSTR;
        float m = -1e30f;
        for (int k = lane; k < S_; k += 32) m = fmaxf(m, row[k]);
#pragma unroll
        for (int o = 16; o; o >>= 1) m = fmaxf(m, __shfl_xor_sync(~0u, m, o));
        float sum = 0.f;
        for (int k = lane; k < S_; k += 32) {
            float e = __expf(row[k] - m);
            row[k] = e;
            sum += e;
        }
#pragma unroll
        for (int o = 16; o; o >>= 1) sum += __shfl_xor_sync(~0u, sum, o);
        float inv = 1.f / sum;
        for (int k = lane; k < S_; k += 32) row[k] *= inv;
    }
    __syncthreads();

    // ---- write att (coalesced) + convert sc to tf32 in place ----
    {
        float* abase = att + ((size_t)(b * H_ + h) * S_ + q0) * S_;
        for (int idx = tid; idx < QT * S_; idx += NTHR) {
            int si = (idx >> 10) * SCSTR + (idx & 1023);
            float v = sc[si];
            abase[(size_t)(idx >> 10) * S_ + (idx & 1023)] = v;
            sc[si] = to_tf32(v);
        }
    }
    KV_STS(0);          // stage V[0]
    KV_LDG(128, 1);
    __syncthreads();    // sc(tf32) + kv[0](V) visible

    // ---- ctx = P @ V : warp covers all 64 dims, k-slice cg*16..+16/chunk ----
    float acc3[8][4];
#pragma unroll
    for (int j = 0; j < 8; j++)
#pragma unroll
        for (int v = 0; v < 4; v++) acc3[j][v] = 0.f;

    for (int c = 0; c < 8; c++) {
        const float* kvc = kv + (c & 1) * KVTILE;
        if (c < 7) KV_STS((c + 1) & 1);
        if (c < 6) KV_LDG(128, c + 2);

#pragma unroll
        for (int s = 0; s < 2; s++) {
            int kl = cg * 16 + s * 8;        // chunk-local k offset
            int kg = c * 128 + kl;           // global
            uint32_t af[4];
            af[0] = __float_as_uint(sc[(rbase + g)     * SCSTR + kg + a]);
            af[1] = __float_as_uint(sc[(rbase + g + 8) * SCSTR + kg + a]);
            af[2] = __float_as_uint(sc[(rbase + g)     * SCSTR + kg + 4 + a]);
            af[3] = __float_as_uint(sc[(rbase + g + 8) * SCSTR + kg + 4 + a]);
#pragma unroll
            for (int j = 0; j < 8; j++) {
                uint32_t bf[2];
                bf[0] = __float_as_uint(kvc[(kl + a)     * KVSTR + j * 8 + g]);
                bf[1] = __float_as_uint(kvc[(kl + 4 + a) * KVSTR + j * 8 + g]);
                mma_tf32(acc3[j], af, bf);
            }
        }
        __syncthreads();
    }
#undef KV_LDG
#undef KV_STS
#undef MASK_LDG

    // ---- cross-warp reduction over the 8 k-slice warps (staged in sc) ----
    // red[w][row16][dim64], row stride RSTR; sc region is dead now.
    {
        float* red = sc;
#pragma unroll
        for (int j = 0; j < 8; j++) {
            *(float2*)(red + (w * 16 + g)     * RSTR + j * 8 + a * 2) =
                make_float2(acc3[j][0], acc3[j][1]);
            *(float2*)(red + (w * 16 + g + 8) * RSTR + j * 8 + a * 2) =
                make_float2(acc3[j][2], acc3[j][3]);
        }
        __syncthreads();

        // 2048 outputs = 512 float4: thread t -> (rg, row, 4 dims)
        int rg  = tid >> 8;            // 0..1
        int row = (tid >> 4) & 15;     // 0..15
        int d4  = (tid & 15) * 4;      // 0..60
        float4 s = make_float4(0.f, 0.f, 0.f, 0.f);
#pragma unroll
        for (int k = 0; k < 8; k++) {
            const float* p = red + ((rg * 8 + k) * 16 + row) * RSTR + d4;
            s.x += p[0]; s.y += p[1]; s.z += p[2]; s.w += p[3];
        }
        int rowg = b * S_ + q0 + rg * 16 + row;
        *(float4*)(g_ctx + (size_t)rowg * D_ + h * HD_ + d4) = s;
    }
}

// ---------------------------------------------------------------------------
extern "C" void kernel_launch(void* const* d_in, const int* in_sizes, int n_in,
                              void* d_out, int out_size)
{
    const float* x    = (const float*)d_in[0];
    const float* mask = (const float*)d_in[1];
    const float* Wqkv = (const float*)d_in[2];
    const float* bqkv = (const float*)d_in[3];
    const float* Wo   = (const float*)d_in[4];
    const float* bo   = (const float*)d_in[5];

    float* out = (float*)d_out;                       // [B,S,D]
    float* att = out + (size_t)B_ * S_ * D_;          // [B,H,S,S]

    cudaFuncSetAttribute(attn_kernel,
                         cudaFuncAttributeMaxDynamicSharedMemorySize, ATTN_SMEM);
    cudaFuncSetAttribute(qkv_gemm_kernel,
                         cudaFuncAttributeMaxDynamicSharedMemorySize, GEMM_SMEM);
    cudaFuncSetAttribute(out_gemm_kernel,
                         cudaFuncAttributeMaxDynamicSharedMemorySize, GEMM_SMEM);

    // 1) fused QKV projection (tf32 tensor cores)
    {
        dim3 grid(QKVN / 128, M_ / BM_T);
        qkv_gemm_kernel<<<grid, 256, GEMM_SMEM>>>(x, Wqkv, bqkv);
    }
    // 2) fused attention (scores + softmax + att write + ctx)
    {
        dim3 grid(S_ / QT, H_, B_);
        attn_kernel<<<grid, NTHR, ATTN_SMEM>>>(mask, att);
    }
    // 3) output projection
    {
        dim3 grid(D_ / 128, M_ / BM_T);
        out_gemm_kernel<<<grid, 256, GEMM_SMEM>>>(Wo, bo, out);
    }
}